// round 16
// baseline (speedup 1.0000x reference)
#include <cuda_runtime.h>
#include <cuda_fp16.h>
#include <math.h>
#include <stdint.h>

#define BATCH   4
#define SEQ     2048
#define DMODEL  1024
#define DFF     4096
#define DK      64
#define MROWS   (BATCH*SEQ)      // 8192
#define BHCNT   (BATCH*16)       // 64
#define QKVN    (3*DMODEL)       // 3072

// ---------------- scratch (static device globals) ----------------
__device__ __half g_ln1[(size_t)MROWS*DMODEL];
__device__ __half g_ln2[(size_t)MROWS*DMODEL];
__device__ __half g_att[(size_t)MROWS*DMODEL];
__device__ __half g_ff [(size_t)MROWS*DFF];
__device__ __half g_qkv[(size_t)MROWS*QKVN];
__device__ __half g_x1 [(size_t)MROWS*DMODEL];   // fp16 residual stream
__device__ float  g_bqkv[QKVN];
// transposed weights: [N][K] fp16
__device__ __half g_wqkv[(size_t)QKVN*DMODEL];
__device__ __half g_wo[(size_t)DMODEL*DMODEL];
__device__ __half g_w1[(size_t)DFF*DMODEL];
__device__ __half g_w2[(size_t)DMODEL*DFF];

// ---------------- PTX helpers (compute_103-safe) ----------------
__device__ __forceinline__ uint32_t smem_u32(const void* p){
    uint32_t a;
    asm("{ .reg .u64 t; cvta.to.shared.u64 t, %1; cvt.u32.u64 %0, t; }" : "=r"(a) : "l"(p));
    return a;
}
#define CPA16(smaddr, gptr) \
    asm volatile("cp.async.cg.shared.global [%0], [%1], 16;" :: "r"(smaddr), "l"(gptr))
#define CPA_COMMIT() asm volatile("cp.async.commit_group;" ::: "memory")
#define CPA_WAIT1()  asm volatile("cp.async.wait_group 1;" ::: "memory")
#define CPA_WAIT0()  asm volatile("cp.async.wait_group 0;" ::: "memory")
#define LDSM4(r, addr) \
    asm volatile("ldmatrix.sync.aligned.m8n8.x4.shared.b16 {%0,%1,%2,%3}, [%4];" \
        : "=r"((r)[0]), "=r"((r)[1]), "=r"((r)[2]), "=r"((r)[3]) : "r"(addr))
#define LDSM4T(r, addr) \
    asm volatile("ldmatrix.sync.aligned.m8n8.x4.trans.shared.b16 {%0,%1,%2,%3}, [%4];" \
        : "=r"((r)[0]), "=r"((r)[1]), "=r"((r)[2]), "=r"((r)[3]) : "r"(addr))

__device__ __forceinline__ void mma_fp16(float* c, const uint32_t* a, const uint32_t* b){
    asm volatile("mma.sync.aligned.m16n8k16.row.col.f32.f16.f16.f32 "
        "{%0,%1,%2,%3}, {%4,%5,%6,%7}, {%8,%9}, {%0,%1,%2,%3};"
        : "+f"(c[0]), "+f"(c[1]), "+f"(c[2]), "+f"(c[3])
        : "r"(a[0]), "r"(a[1]), "r"(a[2]), "r"(a[3]), "r"(b[0]), "r"(b[1]));
}

// ---------------- merged weight transpose: 6 weights in one launch ----------------
__global__ void wsplit_all_kernel(
    const float* Wq, const float* Wk, const float* Wv, const float* Wo,
    const float* W1, const float* W2,
    __half* Tqkv, __half* To, __half* T1, __half* T2)
{
    int blk = blockIdx.x;
    const float* W; __half* T; int K, N, ntx, rel;
    if (blk < 4096) {
        K = DMODEL; N = DMODEL; ntx = 32;
        int w = blk >> 10; rel = blk & 1023;
        if (w == 0)      { W = Wq; T = Tqkv; }
        else if (w == 1) { W = Wk; T = Tqkv + (size_t)DMODEL*DMODEL; }
        else if (w == 2) { W = Wv; T = Tqkv + (size_t)2*DMODEL*DMODEL; }
        else             { W = Wo; T = To; }
    } else if (blk < 8192) {
        W = W1; T = T1; K = DMODEL; N = DFF; ntx = DFF/32; rel = blk - 4096;
    } else {
        W = W2; T = T2; K = DFF; N = DMODEL; ntx = DMODEL/32; rel = blk - 8192;
    }
    const int n0 = (rel % ntx) * 32, k0 = (rel / ntx) * 32;

    __shared__ float t[32][33];
    const int tx = threadIdx.x, ty = threadIdx.y;   // (32, 8)
    #pragma unroll
    for (int i = 0; i < 32; i += 8)
        t[ty + i][tx] = W[(size_t)(k0 + ty + i) * N + n0 + tx];
    __syncthreads();
    #pragma unroll
    for (int i = 0; i < 32; i += 8)
        T[(size_t)(n0 + ty + i) * K + k0 + tx] = __float2half(t[tx][ty + i]);
}

// ---------------- bias concat ----------------
__global__ void bcat_kernel(const float* __restrict__ bq, const float* __restrict__ bk,
                            const float* __restrict__ bv, float* __restrict__ o)
{
    int i = blockIdx.x * 256 + threadIdx.x;
    if (i < DMODEL)            o[i] = bq[i];
    else if (i < 2*DMODEL)     o[i] = bk[i - DMODEL];
    else if (i < 3*DMODEL)     o[i] = bv[i - 2*DMODEL];
}

// ---------------- LayerNorm -> fp16 (templated input type) ----------------
template<typename TIN>
__global__ void ln_kernel(const TIN* __restrict__ in, const float* __restrict__ gam,
                          const float* __restrict__ bet, __half* __restrict__ O)
{
    int row = blockIdx.x;
    float v0, v1, v2, v3;
    if (sizeof(TIN) == 4) {
        const float4* xp = reinterpret_cast<const float4*>((const float*)in + (size_t)row * DMODEL);
        float4 v = xp[threadIdx.x];
        v0 = v.x; v1 = v.y; v2 = v.z; v3 = v.w;
    } else {
        const __half2* xp = reinterpret_cast<const __half2*>((const __half*)in + (size_t)row * DMODEL);
        float2 a = __half22float2(xp[threadIdx.x * 2]);
        float2 b = __half22float2(xp[threadIdx.x * 2 + 1]);
        v0 = a.x; v1 = a.y; v2 = b.x; v3 = b.y;
    }
    float s  = v0 + v1 + v2 + v3;
    float ss = v0*v0 + v1*v1 + v2*v2 + v3*v3;
    __shared__ float red[16];
    #pragma unroll
    for (int o = 16; o; o >>= 1) {
        s  += __shfl_xor_sync(0xffffffffu, s,  o);
        ss += __shfl_xor_sync(0xffffffffu, ss, o);
    }
    int w = threadIdx.x >> 5, l = threadIdx.x & 31;
    if (l == 0) { red[w] = s; red[w + 8] = ss; }
    __syncthreads();
    if (threadIdx.x < 32) {
        s  = red[l & 7];  ss = red[(l & 7) + 8];
        #pragma unroll
        for (int o = 4; o; o >>= 1) {
            s  += __shfl_xor_sync(0xffffffffu, s,  o);
            ss += __shfl_xor_sync(0xffffffffu, ss, o);
        }
        if (l == 0) { red[0] = s; red[1] = ss; }
    }
    __syncthreads();
    float mean = red[0] * (1.0f / DMODEL);
    float var  = red[1] * (1.0f / DMODEL) - mean * mean;
    float rstd = rsqrtf(var + 1e-5f);
    float4 gg = reinterpret_cast<const float4*>(gam)[threadIdx.x];
    float4 bb = reinterpret_cast<const float4*>(bet)[threadIdx.x];
    float o0 = (v0 - mean) * rstd * gg.x + bb.x;
    float o1 = (v1 - mean) * rstd * gg.y + bb.y;
    float o2 = (v2 - mean) * rstd * gg.z + bb.z;
    float o3 = (v3 - mean) * rstd * gg.w + bb.w;
    size_t base = (size_t)row * DMODEL + threadIdx.x * 4;
    *reinterpret_cast<__half2*>(O + base)     = __floats2half2_rn(o0, o1);
    *reinterpret_cast<__half2*>(O + base + 2) = __floats2half2_rn(o2, o3);
}

// ---------------- warp-MMA fp16 GEMM: C[M,N] = A[M,K] @ B[N,K]^T + bias ----------------
// CTA 128x128, warp 32x64, fp32 acc, 3-stage cp.async pipeline,
// register double-buffered B fragments.
// EPI: 1 = bias+GELU -> fp16 Ch
//      2 = bias + fp32 residual R -> fp16 Ch      (Wo proj: x1 = attnWo + x)
//      3 = bias + fp16 residual Rh -> fp32 C      (FFN2: out = ffn + x1)
//      5 = bias, Q-third scaled 0.125 -> fp16 Ch  (QKV)
template<int EPI>
__global__ void __launch_bounds__(256) tgemm_kernel(
    const __half* __restrict__ A, const __half* __restrict__ B,
    const float* __restrict__ bias, const float* __restrict__ R,
    const __half* __restrict__ Rh,
    float* __restrict__ C, __half* __restrict__ Ch,
    int K, int N)
{
    extern __shared__ char sm_raw[];
    uint32_t sbase = smem_u32(sm_raw);
    sbase = (sbase + 127) & ~127u;

    const int tid = threadIdx.x;
    const int m0 = blockIdx.y * 128, n0 = blockIdx.x * 128;
    const int wid = tid >> 5, lane = tid & 31;
    const int wm = wid & 3, wn = wid >> 2;   // warp tile: 32 (m) x 64 (n)

    const int pr = tid >> 1;
    const int ph = (tid & 1) * 4;
    const __half* gA = A + (size_t)(m0 + pr) * K + ph * 8;
    const __half* gB = B + (size_t)(n0 + pr) * K + ph * 8;
    uint32_t sseg[4];
    #pragma unroll
    for (int i = 0; i < 4; i++) sseg[i] = (uint32_t)(((ph + i) ^ (pr & 7)) << 4);
    const uint32_t arow = sbase + pr * 128;
    const uint32_t brow = sbase + 16384 + pr * 128;

    float acc[2][8][4];
    #pragma unroll
    for (int a = 0; a < 2; a++)
        #pragma unroll
        for (int b = 0; b < 8; b++)
            #pragma unroll
            for (int c = 0; c < 4; c++) acc[a][b][c] = 0.f;

    const int nkc = K >> 6;   // k-chunks of 64

    #pragma unroll
    for (int c = 0; c < 2; c++) {
        const uint32_t so = (uint32_t)(c * 32768);
        const __half* ga = gA + (size_t)c * 64;
        const __half* gb = gB + (size_t)c * 64;
        #pragma unroll
        for (int i = 0; i < 4; i++) {
            CPA16(arow + so + sseg[i], ga + i * 8);
            CPA16(brow + so + sseg[i], gb + i * 8);
        }
        CPA_COMMIT();
    }

    int a_r[2], b_r[4];
    #pragma unroll
    for (int mt = 0; mt < 2; mt++) a_r[mt] = wm * 32 + mt * 16 + (lane & 15);
    #pragma unroll
    for (int p = 0; p < 4; p++)
        b_r[p] = wn * 64 + p * 16 + ((lane >> 4) << 3) + (lane & 7);
    const int a_s0 = (lane >> 4);
    const int b_s0 = ((lane >> 3) & 1);

    int st = 0, pst = 2;
    for (int kc = 0; kc < nkc; kc++) {
        CPA_WAIT1();
        __syncthreads();

        if (kc + 2 < nkc) {
            const uint32_t so = (uint32_t)(pst * 32768);
            const __half* ga = gA + (size_t)(kc + 2) * 64;
            const __half* gb = gB + (size_t)(kc + 2) * 64;
            #pragma unroll
            for (int i = 0; i < 4; i++) {
                CPA16(arow + so + sseg[i], ga + i * 8);
                CPA16(brow + so + sseg[i], gb + i * 8);
            }
        }
        CPA_COMMIT();

        const uint32_t sA = sbase + (uint32_t)(st * 32768);
        const uint32_t sB = sA + 16384;

        // ---- register double-buffered fragment pipeline over kt ----
        uint32_t af[2][4];
        uint32_t bf[2][4][4];
        #pragma unroll
        for (int mt = 0; mt < 2; mt++) {
            const int r = a_r[mt];
            LDSM4(af[mt], sA + r * 128 + ((a_s0 ^ (r & 7)) << 4));
        }
        #pragma unroll
        for (int p = 0; p < 4; p++) {
            const int r = b_r[p];
            LDSM4(bf[0][p], sB + r * 128 + ((b_s0 ^ (r & 7)) << 4));
        }
        #pragma unroll
        for (int kt = 0; kt < 4; kt++) {
            const int cur = kt & 1, nxt = cur ^ 1;
            if (kt < 3) {
                #pragma unroll
                for (int p = 0; p < 4; p++) {
                    const int r = b_r[p];
                    const int s = (kt + 1) * 2 + b_s0;
                    LDSM4(bf[nxt][p], sB + r * 128 + ((s ^ (r & 7)) << 4));
                }
            }
            #pragma unroll
            for (int mt = 0; mt < 2; mt++)
                #pragma unroll
                for (int p = 0; p < 4; p++) {
                    mma_fp16(acc[mt][2*p],   af[mt], &bf[cur][p][0]);
                    mma_fp16(acc[mt][2*p+1], af[mt], &bf[cur][p][2]);
                }
            if (kt < 3) {
                #pragma unroll
                for (int mt = 0; mt < 2; mt++) {
                    const int r = a_r[mt];
                    const int s = (kt + 1) * 2 + a_s0;
                    LDSM4(af[mt], sA + r * 128 + ((s ^ (r & 7)) << 4));
                }
            }
        }
        pst = st; st = (st == 2) ? 0 : st + 1;
    }

    // ---- epilogue ----
    const int er0 = m0 + wm * 32;
    const int ec0 = n0 + wn * 64;
    #pragma unroll
    for (int mt = 0; mt < 2; mt++) {
        #pragma unroll
        for (int nt = 0; nt < 8; nt++) {
            const int col = ec0 + nt * 8 + (lane & 3) * 2;
            const float2 bv = *reinterpret_cast<const float2*>(bias + col);
            const float* a = acc[mt][nt];
            #pragma unroll
            for (int half_i = 0; half_i < 2; half_i++) {
                const int row = er0 + mt * 16 + (lane >> 2) + half_i * 8;
                float v0 = a[half_i * 2 + 0] + bv.x;
                float v1 = a[half_i * 2 + 1] + bv.y;
                size_t o = (size_t)row * N + col;
                if (EPI == 1) {
                    v0 = 0.5f * v0 * (1.0f + erff(v0 * 0.70710678118654752f));
                    v1 = 0.5f * v1 * (1.0f + erff(v1 * 0.70710678118654752f));
                    *reinterpret_cast<__half2*>(Ch + o) = __floats2half2_rn(v0, v1);
                } else if (EPI == 5) {
                    const float sc = (col < DMODEL) ? 0.125f : 1.0f;
                    *reinterpret_cast<__half2*>(Ch + o) = __floats2half2_rn(v0 * sc, v1 * sc);
                } else if (EPI == 2) {
                    const float2 rv = *reinterpret_cast<const float2*>(R + o);
                    *reinterpret_cast<__half2*>(Ch + o) = __floats2half2_rn(v0 + rv.x, v1 + rv.y);
                } else {  // EPI == 3
                    const float2 rv = __half22float2(*reinterpret_cast<const __half2*>(Rh + o));
                    float2 ov; ov.x = v0 + rv.x; ov.y = v1 + rv.y;
                    *reinterpret_cast<float2*>(C + o) = ov;
                }
            }
        }
    }
}

// ---------------- fused flash attention (fp16 MMA, online softmax) ----------------
// Single __syncthreads per kv-tile: prefetch issued AFTER the barrier, so the
// recycled stage was fully read in the iteration all warps just completed.
__global__ void __launch_bounds__(256) flash_kernel(
    const __half* __restrict__ QKV, __half* __restrict__ Om)
{
    const int it = gridDim.x - 1 - blockIdx.x;
    const int bh = blockIdx.y;
    const int b = bh >> 4, h = bh & 15;
    extern __shared__ char sm_raw[];
    uint32_t sbase = smem_u32(sm_raw);
    sbase = (sbase + 127) & ~127u;
    const uint32_t sQ  = sbase;
    const uint32_t sKV = sbase + 16384;

    const int tid = threadIdx.x;
    const int wid = tid >> 5, lane = tid & 31;

    const int pr = tid >> 1;
    const int phh = (tid & 1) * 4;
    uint32_t sseg[4];
    #pragma unroll
    for (int i = 0; i < 4; i++) sseg[i] = (uint32_t)(((phh + i) ^ (pr & 7)) << 4);

    const __half* gQ = QKV + (size_t)(b*SEQ + it*128 + pr)*QKVN + h*64 + phh*8;
    #pragma unroll
    for (int i = 0; i < 4; i++) CPA16(sQ + pr*128 + sseg[i], gQ + i*8);
    CPA_COMMIT();

    const __half* gK = QKV + (size_t)(b*SEQ + pr)*QKVN + DMODEL   + h*64 + phh*8;
    const __half* gV = QKV + (size_t)(b*SEQ + pr)*QKVN + 2*DMODEL + h*64 + phh*8;
    #pragma unroll
    for (int i = 0; i < 4; i++) {
        CPA16(sKV + pr*128 + sseg[i],          gK + i*8);
        CPA16(sKV + 16384 + pr*128 + sseg[i],  gV + i*8);
    }
    CPA_COMMIT();

    uint32_t qf[4][4];
    float oacc[8][4];
    #pragma unroll
    for (int i = 0; i < 8; i++)
        #pragma unroll
        for (int j = 0; j < 4; j++) oacc[i][j] = 0.f;
    float m0 = -1e30f, m1 = -1e30f, l0 = 0.f, l1 = 0.f;

    const int a_row = wid*16 + (lane & 15);
    const int a_sg  = (lane >> 4);
    const int b_rw  = ((lane >> 4) << 3) + (lane & 7);
    const int b_sg  = ((lane >> 3) & 1);
    const int vk_r  = ((lane >> 3) & 1)*8 + (lane & 7);
    const int vn_s  = (lane >> 4);

    for (int jt = 0; jt <= it; jt++) {
        const int st = jt & 1;
        CPA_WAIT0();          // all issued groups done (tile jt's KV was the last)
        __syncthreads();      // all warps finished reading the stage being recycled next

        if (jt < it) {        // prefetch tile jt+1 into the opposite stage
            const uint32_t so = sKV + (uint32_t)(((jt+1)&1) * 32768);
            const __half* gk = gK + (size_t)((jt+1)*128)*QKVN;
            const __half* gv = gV + (size_t)((jt+1)*128)*QKVN;
            #pragma unroll
            for (int i = 0; i < 4; i++) {
                CPA16(so + pr*128 + sseg[i],         gk + i*8);
                CPA16(so + 16384 + pr*128 + sseg[i], gv + i*8);
            }
            CPA_COMMIT();
        }

        if (jt == 0) {
            #pragma unroll
            for (int t = 0; t < 4; t++)
                LDSM4(qf[t], sQ + a_row*128 + (((2*t + a_sg) ^ (a_row & 7)) << 4));
        }

        const uint32_t sK = sKV + (uint32_t)(st * 32768);
        const uint32_t sV = sK + 16384;

        float sacc[16][4];
        #pragma unroll
        for (int i = 0; i < 16; i++)
            #pragma unroll
            for (int j = 0; j < 4; j++) sacc[i][j] = 0.f;
        #pragma unroll
        for (int p = 0; p < 8; p++) {
            uint32_t bt[4][4];
            const int r = p*16 + b_rw;
            #pragma unroll
            for (int t = 0; t < 4; t++)
                LDSM4(bt[t], sK + r*128 + (((2*t + b_sg) ^ (r & 7)) << 4));
            #pragma unroll
            for (int t = 0; t < 4; t++) {
                mma_fp16(sacc[2*p],   qf[t], &bt[t][0]);
                mma_fp16(sacc[2*p+1], qf[t], &bt[t][2]);
            }
        }

        if (jt == it) {
            const int grow = wid*16 + (lane >> 2);
            #pragma unroll
            for (int nt = 0; nt < 16; nt++) {
                #pragma unroll
                for (int c = 0; c < 2; c++) {
                    const int gcol = nt*8 + (lane & 3)*2 + c;
                    if (gcol > grow)     sacc[nt][c]     = -1e30f;
                    if (gcol > grow + 8) sacc[nt][2 + c] = -1e30f;
                }
            }
        }

        float tm0 = -1e30f, tm1 = -1e30f;
        #pragma unroll
        for (int nt = 0; nt < 16; nt++) {
            tm0 = fmaxf(tm0, fmaxf(sacc[nt][0], sacc[nt][1]));
            tm1 = fmaxf(tm1, fmaxf(sacc[nt][2], sacc[nt][3]));
        }
        tm0 = fmaxf(tm0, __shfl_xor_sync(0xffffffffu, tm0, 1));
        tm0 = fmaxf(tm0, __shfl_xor_sync(0xffffffffu, tm0, 2));
        tm1 = fmaxf(tm1, __shfl_xor_sync(0xffffffffu, tm1, 1));
        tm1 = fmaxf(tm1, __shfl_xor_sync(0xffffffffu, tm1, 2));
        const float mn0 = fmaxf(m0, tm0), mn1 = fmaxf(m1, tm1);
        const float al0 = __expf(m0 - mn0), al1 = __expf(m1 - mn1);

        uint32_t pf[16], pg[16];
        float rs0 = 0.f, rs1 = 0.f;
        #pragma unroll
        for (int nt = 0; nt < 16; nt++) {
            float p0 = __expf(sacc[nt][0] - mn0);
            float p1 = __expf(sacc[nt][1] - mn0);
            float p2 = __expf(sacc[nt][2] - mn1);
            float p3 = __expf(sacc[nt][3] - mn1);
            rs0 += p0 + p1; rs1 += p2 + p3;
            __half2 hp0 = __floats2half2_rn(p0, p1);
            __half2 hp1 = __floats2half2_rn(p2, p3);
            pf[nt] = *reinterpret_cast<uint32_t*>(&hp0);
            pg[nt] = *reinterpret_cast<uint32_t*>(&hp1);
        }
        rs0 += __shfl_xor_sync(0xffffffffu, rs0, 1);
        rs0 += __shfl_xor_sync(0xffffffffu, rs0, 2);
        rs1 += __shfl_xor_sync(0xffffffffu, rs1, 1);
        rs1 += __shfl_xor_sync(0xffffffffu, rs1, 2);
        l0 = l0 * al0 + rs0;  l1 = l1 * al1 + rs1;
        m0 = mn0;  m1 = mn1;
        #pragma unroll
        for (int nt = 0; nt < 8; nt++) {
            oacc[nt][0] *= al0; oacc[nt][1] *= al0;
            oacc[nt][2] *= al1; oacc[nt][3] *= al1;
        }

        #pragma unroll
        for (int t = 0; t < 8; t++) {
            uint32_t a[4] = { pf[2*t], pg[2*t], pf[2*t+1], pg[2*t+1] };
            const int kr = t*16 + vk_r;
            #pragma unroll
            for (int pp = 0; pp < 4; pp++) {
                uint32_t bt[4];
                LDSM4T(bt, sV + kr*128 + (((2*pp + vn_s) ^ (kr & 7)) << 4));
                mma_fp16(oacc[2*pp],   a, &bt[0]);
                mma_fp16(oacc[2*pp+1], a, &bt[2]);
            }
        }
        // no bottom barrier: next iteration's top barrier protects stage recycling
    }

    const float inv0 = 1.0f / l0, inv1 = 1.0f / l1;
    const int row0 = it*128 + wid*16 + (lane >> 2);
    #pragma unroll
    for (int nt = 0; nt < 8; nt++) {
        const int col = h*64 + nt*8 + (lane & 3)*2;
        size_t o0 = (size_t)(b*SEQ + row0)     * DMODEL + col;
        size_t o1 = (size_t)(b*SEQ + row0 + 8) * DMODEL + col;
        *reinterpret_cast<__half2*>(Om + o0) = __floats2half2_rn(oacc[nt][0]*inv0, oacc[nt][1]*inv0);
        *reinterpret_cast<__half2*>(Om + o1) = __floats2half2_rn(oacc[nt][2]*inv1, oacc[nt][3]*inv1);
    }
}

// ---------------- orchestration ----------------
#define TGEMM_SMEM (3*32768 + 256)
#define FLASH_SMEM (16384 + 2*32768 + 256)

extern "C" void kernel_launch(void* const* d_in, const int* in_sizes, int n_in,
                              void* d_out, int out_size)
{
    (void)in_sizes; (void)n_in; (void)out_size;
    const float* x    = (const float*)d_in[0];
    const float* Wq   = (const float*)d_in[1];
    const float* bq   = (const float*)d_in[2];
    const float* Wk   = (const float*)d_in[3];
    const float* bk   = (const float*)d_in[4];
    const float* Wv   = (const float*)d_in[5];
    const float* bv   = (const float*)d_in[6];
    const float* Wo   = (const float*)d_in[7];
    const float* bo   = (const float*)d_in[8];
    const float* ln1g = (const float*)d_in[9];
    const float* ln1b = (const float*)d_in[10];
    const float* ln2g = (const float*)d_in[11];
    const float* ln2b = (const float*)d_in[12];
    const float* W1   = (const float*)d_in[13];
    const float* b1   = (const float*)d_in[14];
    const float* W2   = (const float*)d_in[15];
    const float* b2   = (const float*)d_in[16];
    float* out = (float*)d_out;

    cudaFuncSetAttribute(tgemm_kernel<1>, cudaFuncAttributeMaxDynamicSharedMemorySize, TGEMM_SMEM);
    cudaFuncSetAttribute(tgemm_kernel<2>, cudaFuncAttributeMaxDynamicSharedMemorySize, TGEMM_SMEM);
    cudaFuncSetAttribute(tgemm_kernel<3>, cudaFuncAttributeMaxDynamicSharedMemorySize, TGEMM_SMEM);
    cudaFuncSetAttribute(tgemm_kernel<5>, cudaFuncAttributeMaxDynamicSharedMemorySize, TGEMM_SMEM);
    cudaFuncSetAttribute(flash_kernel,    cudaFuncAttributeMaxDynamicSharedMemorySize, FLASH_SMEM);

    __half *p_ln1, *p_ln2, *p_att, *p_ff, *p_qkv, *p_x1;
    __half *p_wqkv, *p_wo, *p_w1, *p_w2;
    float *p_bqkv;
    cudaGetSymbolAddress((void**)&p_ln1,  g_ln1);
    cudaGetSymbolAddress((void**)&p_ln2,  g_ln2);
    cudaGetSymbolAddress((void**)&p_att,  g_att);
    cudaGetSymbolAddress((void**)&p_ff,   g_ff);
    cudaGetSymbolAddress((void**)&p_qkv,  g_qkv);
    cudaGetSymbolAddress((void**)&p_wqkv, g_wqkv);
    cudaGetSymbolAddress((void**)&p_wo,   g_wo);
    cudaGetSymbolAddress((void**)&p_w1,   g_w1);
    cudaGetSymbolAddress((void**)&p_w2,   g_w2);
    cudaGetSymbolAddress((void**)&p_x1,   g_x1);
    cudaGetSymbolAddress((void**)&p_bqkv, g_bqkv);

    wsplit_all_kernel<<<12288, dim3(32, 8)>>>(Wq, Wk, Wv, Wo, W1, W2,
                                              p_wqkv, p_wo, p_w1, p_w2);
    bcat_kernel<<<QKVN/256, 256>>>(bq, bk, bv, p_bqkv);

    ln_kernel<float><<<MROWS, 256>>>(x, ln1g, ln1b, p_ln1);

    // fused QKV projection (Q pre-scaled by 1/8)
    tgemm_kernel<5><<<dim3(QKVN/128, MROWS/128), 256, TGEMM_SMEM>>>(
        p_ln1, p_wqkv, p_bqkv, nullptr, nullptr, nullptr, p_qkv, DMODEL, QKVN);

    flash_kernel<<<dim3(SEQ/128, BHCNT), 256, FLASH_SMEM>>>(p_qkv, p_att);

    const dim3 gDD(DMODEL/128, MROWS/128);   // (8, 64)
    // Wo projection + residual(x fp32) -> x1 fp16
    tgemm_kernel<2><<<gDD, 256, TGEMM_SMEM>>>(p_att, p_wo, bo, x, nullptr, nullptr, p_x1, DMODEL, DMODEL);
    // LN2 reads fp16 x1
    ln_kernel<__half><<<MROWS, 256>>>(p_x1, ln2g, ln2b, p_ln2);
    // FFN1 + GELU -> fp16
    tgemm_kernel<1><<<dim3(DFF/128, MROWS/128), 256, TGEMM_SMEM>>>(
        p_ln2, p_w1, b1, nullptr, nullptr, nullptr, p_ff, DMODEL, DFF);
    // FFN2 + residual(x1 fp16) -> fp32 out
    tgemm_kernel<3><<<gDD, 256, TGEMM_SMEM>>>(p_ff, p_w2, b2, nullptr, p_x1, out, nullptr, DFF, DMODEL);
}

// round 17
// speedup vs baseline: 1.0033x; 1.0033x over previous
#include <cuda_runtime.h>
#include <cuda_fp16.h>
#include <math.h>
#include <stdint.h>

#define BATCH   4
#define SEQ     2048
#define DMODEL  1024
#define DFF     4096
#define DK      64
#define MROWS   (BATCH*SEQ)      // 8192
#define BHCNT   (BATCH*16)       // 64
#define QKVN    (3*DMODEL)       // 3072

// ---------------- scratch (static device globals) ----------------
__device__ __half g_ln1[(size_t)MROWS*DMODEL];
__device__ __half g_ln2[(size_t)MROWS*DMODEL];
__device__ __half g_att[(size_t)MROWS*DMODEL];
__device__ __half g_ff [(size_t)MROWS*DFF];
__device__ __half g_qkv[(size_t)MROWS*QKVN];
__device__ __half g_x1 [(size_t)MROWS*DMODEL];   // fp16 residual stream
__device__ float  g_bqkv[QKVN];
// transposed weights: [N][K] fp16
__device__ __half g_wqkv[(size_t)QKVN*DMODEL];
__device__ __half g_wo[(size_t)DMODEL*DMODEL];
__device__ __half g_w1[(size_t)DFF*DMODEL];
__device__ __half g_w2[(size_t)DMODEL*DFF];

// ---------------- PTX helpers (compute_103-safe) ----------------
__device__ __forceinline__ uint32_t smem_u32(const void* p){
    uint32_t a;
    asm("{ .reg .u64 t; cvta.to.shared.u64 t, %1; cvt.u32.u64 %0, t; }" : "=r"(a) : "l"(p));
    return a;
}
#define CPA16(smaddr, gptr) \
    asm volatile("cp.async.cg.shared.global [%0], [%1], 16;" :: "r"(smaddr), "l"(gptr))
#define CPA_COMMIT() asm volatile("cp.async.commit_group;" ::: "memory")
#define CPA_WAIT1()  asm volatile("cp.async.wait_group 1;" ::: "memory")
#define CPA_WAIT0()  asm volatile("cp.async.wait_group 0;" ::: "memory")
#define LDSM4(r, addr) \
    asm volatile("ldmatrix.sync.aligned.m8n8.x4.shared.b16 {%0,%1,%2,%3}, [%4];" \
        : "=r"((r)[0]), "=r"((r)[1]), "=r"((r)[2]), "=r"((r)[3]) : "r"(addr))
#define LDSM4T(r, addr) \
    asm volatile("ldmatrix.sync.aligned.m8n8.x4.trans.shared.b16 {%0,%1,%2,%3}, [%4];" \
        : "=r"((r)[0]), "=r"((r)[1]), "=r"((r)[2]), "=r"((r)[3]) : "r"(addr))

__device__ __forceinline__ void mma_fp16(float* c, const uint32_t* a, const uint32_t* b){
    asm volatile("mma.sync.aligned.m16n8k16.row.col.f32.f16.f16.f32 "
        "{%0,%1,%2,%3}, {%4,%5,%6,%7}, {%8,%9}, {%0,%1,%2,%3};"
        : "+f"(c[0]), "+f"(c[1]), "+f"(c[2]), "+f"(c[3])
        : "r"(a[0]), "r"(a[1]), "r"(a[2]), "r"(a[3]), "r"(b[0]), "r"(b[1]));
}

// ---------------- merged weight transpose: 6 weights in one launch ----------------
__global__ void wsplit_all_kernel(
    const float* Wq, const float* Wk, const float* Wv, const float* Wo,
    const float* W1, const float* W2,
    __half* Tqkv, __half* To, __half* T1, __half* T2)
{
    int blk = blockIdx.x;
    const float* W; __half* T; int K, N, ntx, rel;
    if (blk < 4096) {
        K = DMODEL; N = DMODEL; ntx = 32;
        int w = blk >> 10; rel = blk & 1023;
        if (w == 0)      { W = Wq; T = Tqkv; }
        else if (w == 1) { W = Wk; T = Tqkv + (size_t)DMODEL*DMODEL; }
        else if (w == 2) { W = Wv; T = Tqkv + (size_t)2*DMODEL*DMODEL; }
        else             { W = Wo; T = To; }
    } else if (blk < 8192) {
        W = W1; T = T1; K = DMODEL; N = DFF; ntx = DFF/32; rel = blk - 4096;
    } else {
        W = W2; T = T2; K = DFF; N = DMODEL; ntx = DMODEL/32; rel = blk - 8192;
    }
    const int n0 = (rel % ntx) * 32, k0 = (rel / ntx) * 32;

    __shared__ float t[32][33];
    const int tx = threadIdx.x, ty = threadIdx.y;   // (32, 8)
    #pragma unroll
    for (int i = 0; i < 32; i += 8)
        t[ty + i][tx] = W[(size_t)(k0 + ty + i) * N + n0 + tx];
    __syncthreads();
    #pragma unroll
    for (int i = 0; i < 32; i += 8)
        T[(size_t)(n0 + ty + i) * K + k0 + tx] = __float2half(t[tx][ty + i]);
}

// ---------------- bias concat ----------------
__global__ void bcat_kernel(const float* __restrict__ bq, const float* __restrict__ bk,
                            const float* __restrict__ bv, float* __restrict__ o)
{
    int i = blockIdx.x * 256 + threadIdx.x;
    if (i < DMODEL)            o[i] = bq[i];
    else if (i < 2*DMODEL)     o[i] = bk[i - DMODEL];
    else if (i < 3*DMODEL)     o[i] = bv[i - 2*DMODEL];
}

// ---------------- LayerNorm -> fp16 (templated input type) ----------------
template<typename TIN>
__global__ void ln_kernel(const TIN* __restrict__ in, const float* __restrict__ gam,
                          const float* __restrict__ bet, __half* __restrict__ O)
{
    int row = blockIdx.x;
    float v0, v1, v2, v3;
    if (sizeof(TIN) == 4) {
        const float4* xp = reinterpret_cast<const float4*>((const float*)in + (size_t)row * DMODEL);
        float4 v = xp[threadIdx.x];
        v0 = v.x; v1 = v.y; v2 = v.z; v3 = v.w;
    } else {
        const __half2* xp = reinterpret_cast<const __half2*>((const __half*)in + (size_t)row * DMODEL);
        float2 a = __half22float2(xp[threadIdx.x * 2]);
        float2 b = __half22float2(xp[threadIdx.x * 2 + 1]);
        v0 = a.x; v1 = a.y; v2 = b.x; v3 = b.y;
    }
    float s  = v0 + v1 + v2 + v3;
    float ss = v0*v0 + v1*v1 + v2*v2 + v3*v3;
    __shared__ float red[16];
    #pragma unroll
    for (int o = 16; o; o >>= 1) {
        s  += __shfl_xor_sync(0xffffffffu, s,  o);
        ss += __shfl_xor_sync(0xffffffffu, ss, o);
    }
    int w = threadIdx.x >> 5, l = threadIdx.x & 31;
    if (l == 0) { red[w] = s; red[w + 8] = ss; }
    __syncthreads();
    if (threadIdx.x < 32) {
        s  = red[l & 7];  ss = red[(l & 7) + 8];
        #pragma unroll
        for (int o = 4; o; o >>= 1) {
            s  += __shfl_xor_sync(0xffffffffu, s,  o);
            ss += __shfl_xor_sync(0xffffffffu, ss, o);
        }
        if (l == 0) { red[0] = s; red[1] = ss; }
    }
    __syncthreads();
    float mean = red[0] * (1.0f / DMODEL);
    float var  = red[1] * (1.0f / DMODEL) - mean * mean;
    float rstd = rsqrtf(var + 1e-5f);
    float4 gg = reinterpret_cast<const float4*>(gam)[threadIdx.x];
    float4 bb = reinterpret_cast<const float4*>(bet)[threadIdx.x];
    float o0 = (v0 - mean) * rstd * gg.x + bb.x;
    float o1 = (v1 - mean) * rstd * gg.y + bb.y;
    float o2 = (v2 - mean) * rstd * gg.z + bb.z;
    float o3 = (v3 - mean) * rstd * gg.w + bb.w;
    size_t base = (size_t)row * DMODEL + threadIdx.x * 4;
    *reinterpret_cast<__half2*>(O + base)     = __floats2half2_rn(o0, o1);
    *reinterpret_cast<__half2*>(O + base + 2) = __floats2half2_rn(o2, o3);
}

// ---------------- warp-MMA fp16 GEMM: C[M,N] = A[M,K] @ B[N,K]^T + bias ----------------
// CTA 128x128, warp 32x64, fp32 acc, 3-stage cp.async pipeline,
// register double-buffered B fragments.
// EPI: 1 = bias+GELU -> fp16 Ch
//      2 = bias + fp32 residual R -> fp16 Ch      (Wo proj: x1 = attnWo + x)
//      3 = bias + fp16 residual Rh -> fp32 C      (FFN2: out = ffn + x1)
//      5 = bias, Q-third scaled 0.125 -> fp16 Ch  (QKV)
template<int EPI>
__global__ void __launch_bounds__(256) tgemm_kernel(
    const __half* __restrict__ A, const __half* __restrict__ B,
    const float* __restrict__ bias, const float* __restrict__ R,
    const __half* __restrict__ Rh,
    float* __restrict__ C, __half* __restrict__ Ch,
    int K, int N)
{
    extern __shared__ char sm_raw[];
    uint32_t sbase = smem_u32(sm_raw);
    sbase = (sbase + 127) & ~127u;

    const int tid = threadIdx.x;
    const int m0 = blockIdx.y * 128, n0 = blockIdx.x * 128;
    const int wid = tid >> 5, lane = tid & 31;
    const int wm = wid & 3, wn = wid >> 2;   // warp tile: 32 (m) x 64 (n)

    const int pr = tid >> 1;
    const int ph = (tid & 1) * 4;
    const __half* gA = A + (size_t)(m0 + pr) * K + ph * 8;
    const __half* gB = B + (size_t)(n0 + pr) * K + ph * 8;
    uint32_t sseg[4];
    #pragma unroll
    for (int i = 0; i < 4; i++) sseg[i] = (uint32_t)(((ph + i) ^ (pr & 7)) << 4);
    const uint32_t arow = sbase + pr * 128;
    const uint32_t brow = sbase + 16384 + pr * 128;

    float acc[2][8][4];
    #pragma unroll
    for (int a = 0; a < 2; a++)
        #pragma unroll
        for (int b = 0; b < 8; b++)
            #pragma unroll
            for (int c = 0; c < 4; c++) acc[a][b][c] = 0.f;

    const int nkc = K >> 6;   // k-chunks of 64

    #pragma unroll
    for (int c = 0; c < 2; c++) {
        const uint32_t so = (uint32_t)(c * 32768);
        const __half* ga = gA + (size_t)c * 64;
        const __half* gb = gB + (size_t)c * 64;
        #pragma unroll
        for (int i = 0; i < 4; i++) {
            CPA16(arow + so + sseg[i], ga + i * 8);
            CPA16(brow + so + sseg[i], gb + i * 8);
        }
        CPA_COMMIT();
    }

    int a_r[2], b_r[4];
    #pragma unroll
    for (int mt = 0; mt < 2; mt++) a_r[mt] = wm * 32 + mt * 16 + (lane & 15);
    #pragma unroll
    for (int p = 0; p < 4; p++)
        b_r[p] = wn * 64 + p * 16 + ((lane >> 4) << 3) + (lane & 7);
    const int a_s0 = (lane >> 4);
    const int b_s0 = ((lane >> 3) & 1);

    int st = 0, pst = 2;
    for (int kc = 0; kc < nkc; kc++) {
        CPA_WAIT1();
        __syncthreads();

        if (kc + 2 < nkc) {
            const uint32_t so = (uint32_t)(pst * 32768);
            const __half* ga = gA + (size_t)(kc + 2) * 64;
            const __half* gb = gB + (size_t)(kc + 2) * 64;
            #pragma unroll
            for (int i = 0; i < 4; i++) {
                CPA16(arow + so + sseg[i], ga + i * 8);
                CPA16(brow + so + sseg[i], gb + i * 8);
            }
        }
        CPA_COMMIT();

        const uint32_t sA = sbase + (uint32_t)(st * 32768);
        const uint32_t sB = sA + 16384;

        // ---- register double-buffered fragment pipeline over kt ----
        uint32_t af[2][4];
        uint32_t bf[2][4][4];
        #pragma unroll
        for (int mt = 0; mt < 2; mt++) {
            const int r = a_r[mt];
            LDSM4(af[mt], sA + r * 128 + ((a_s0 ^ (r & 7)) << 4));
        }
        #pragma unroll
        for (int p = 0; p < 4; p++) {
            const int r = b_r[p];
            LDSM4(bf[0][p], sB + r * 128 + ((b_s0 ^ (r & 7)) << 4));
        }
        #pragma unroll
        for (int kt = 0; kt < 4; kt++) {
            const int cur = kt & 1, nxt = cur ^ 1;
            if (kt < 3) {
                #pragma unroll
                for (int p = 0; p < 4; p++) {
                    const int r = b_r[p];
                    const int s = (kt + 1) * 2 + b_s0;
                    LDSM4(bf[nxt][p], sB + r * 128 + ((s ^ (r & 7)) << 4));
                }
            }
            #pragma unroll
            for (int mt = 0; mt < 2; mt++)
                #pragma unroll
                for (int p = 0; p < 4; p++) {
                    mma_fp16(acc[mt][2*p],   af[mt], &bf[cur][p][0]);
                    mma_fp16(acc[mt][2*p+1], af[mt], &bf[cur][p][2]);
                }
            if (kt < 3) {
                #pragma unroll
                for (int mt = 0; mt < 2; mt++) {
                    const int r = a_r[mt];
                    const int s = (kt + 1) * 2 + a_s0;
                    LDSM4(af[mt], sA + r * 128 + ((s ^ (r & 7)) << 4));
                }
            }
        }
        pst = st; st = (st == 2) ? 0 : st + 1;
    }

    // ---- epilogue ----
    const int er0 = m0 + wm * 32;
    const int ec0 = n0 + wn * 64;
    #pragma unroll
    for (int mt = 0; mt < 2; mt++) {
        #pragma unroll
        for (int nt = 0; nt < 8; nt++) {
            const int col = ec0 + nt * 8 + (lane & 3) * 2;
            const float2 bv = *reinterpret_cast<const float2*>(bias + col);
            const float* a = acc[mt][nt];
            #pragma unroll
            for (int half_i = 0; half_i < 2; half_i++) {
                const int row = er0 + mt * 16 + (lane >> 2) + half_i * 8;
                float v0 = a[half_i * 2 + 0] + bv.x;
                float v1 = a[half_i * 2 + 1] + bv.y;
                size_t o = (size_t)row * N + col;
                if (EPI == 1) {
                    v0 = 0.5f * v0 * (1.0f + erff(v0 * 0.70710678118654752f));
                    v1 = 0.5f * v1 * (1.0f + erff(v1 * 0.70710678118654752f));
                    *reinterpret_cast<__half2*>(Ch + o) = __floats2half2_rn(v0, v1);
                } else if (EPI == 5) {
                    const float sc = (col < DMODEL) ? 0.125f : 1.0f;
                    *reinterpret_cast<__half2*>(Ch + o) = __floats2half2_rn(v0 * sc, v1 * sc);
                } else if (EPI == 2) {
                    const float2 rv = *reinterpret_cast<const float2*>(R + o);
                    *reinterpret_cast<__half2*>(Ch + o) = __floats2half2_rn(v0 + rv.x, v1 + rv.y);
                } else {  // EPI == 3
                    const float2 rv = __half22float2(*reinterpret_cast<const __half2*>(Rh + o));
                    float2 ov; ov.x = v0 + rv.x; ov.y = v1 + rv.y;
                    *reinterpret_cast<float2*>(C + o) = ov;
                }
            }
        }
    }
}

// ---------------- fused flash attention (fp16 MMA, online softmax) ----------------
__global__ void __launch_bounds__(256) flash_kernel(
    const __half* __restrict__ QKV, __half* __restrict__ Om)
{
    const int it = gridDim.x - 1 - blockIdx.x;
    const int bh = blockIdx.y;
    const int b = bh >> 4, h = bh & 15;
    extern __shared__ char sm_raw[];
    uint32_t sbase = smem_u32(sm_raw);
    sbase = (sbase + 127) & ~127u;
    const uint32_t sQ  = sbase;
    const uint32_t sKV = sbase + 16384;

    const int tid = threadIdx.x;
    const int wid = tid >> 5, lane = tid & 31;

    const int pr = tid >> 1;
    const int phh = (tid & 1) * 4;
    uint32_t sseg[4];
    #pragma unroll
    for (int i = 0; i < 4; i++) sseg[i] = (uint32_t)(((phh + i) ^ (pr & 7)) << 4);

    const __half* gQ = QKV + (size_t)(b*SEQ + it*128 + pr)*QKVN + h*64 + phh*8;
    #pragma unroll
    for (int i = 0; i < 4; i++) CPA16(sQ + pr*128 + sseg[i], gQ + i*8);
    CPA_COMMIT();

    const __half* gK = QKV + (size_t)(b*SEQ + pr)*QKVN + DMODEL   + h*64 + phh*8;
    const __half* gV = QKV + (size_t)(b*SEQ + pr)*QKVN + 2*DMODEL + h*64 + phh*8;
    #pragma unroll
    for (int i = 0; i < 4; i++) {
        CPA16(sKV + pr*128 + sseg[i],          gK + i*8);
        CPA16(sKV + 16384 + pr*128 + sseg[i],  gV + i*8);
    }
    CPA_COMMIT();

    uint32_t qf[4][4];
    float oacc[8][4];
    #pragma unroll
    for (int i = 0; i < 8; i++)
        #pragma unroll
        for (int j = 0; j < 4; j++) oacc[i][j] = 0.f;
    float m0 = -1e30f, m1 = -1e30f, l0 = 0.f, l1 = 0.f;

    const int a_row = wid*16 + (lane & 15);
    const int a_sg  = (lane >> 4);
    const int b_rw  = ((lane >> 4) << 3) + (lane & 7);
    const int b_sg  = ((lane >> 3) & 1);
    const int vk_r  = ((lane >> 3) & 1)*8 + (lane & 7);
    const int vn_s  = (lane >> 4);

    for (int jt = 0; jt <= it; jt++) {
        const int st = jt & 1;
        CPA_WAIT0();
        __syncthreads();

        if (jt < it) {
            const uint32_t so = sKV + (uint32_t)(((jt+1)&1) * 32768);
            const __half* gk = gK + (size_t)((jt+1)*128)*QKVN;
            const __half* gv = gV + (size_t)((jt+1)*128)*QKVN;
            #pragma unroll
            for (int i = 0; i < 4; i++) {
                CPA16(so + pr*128 + sseg[i],         gk + i*8);
                CPA16(so + 16384 + pr*128 + sseg[i], gv + i*8);
            }
            CPA_COMMIT();
        }

        if (jt == 0) {
            #pragma unroll
            for (int t = 0; t < 4; t++)
                LDSM4(qf[t], sQ + a_row*128 + (((2*t + a_sg) ^ (a_row & 7)) << 4));
        }

        const uint32_t sK = sKV + (uint32_t)(st * 32768);
        const uint32_t sV = sK + 16384;

        float sacc[16][4];
        #pragma unroll
        for (int i = 0; i < 16; i++)
            #pragma unroll
            for (int j = 0; j < 4; j++) sacc[i][j] = 0.f;
        #pragma unroll
        for (int p = 0; p < 8; p++) {
            uint32_t bt[4][4];
            const int r = p*16 + b_rw;
            #pragma unroll
            for (int t = 0; t < 4; t++)
                LDSM4(bt[t], sK + r*128 + (((2*t + b_sg) ^ (r & 7)) << 4));
            #pragma unroll
            for (int t = 0; t < 4; t++) {
                mma_fp16(sacc[2*p],   qf[t], &bt[t][0]);
                mma_fp16(sacc[2*p+1], qf[t], &bt[t][2]);
            }
        }

        if (jt == it) {
            const int grow = wid*16 + (lane >> 2);
            #pragma unroll
            for (int nt = 0; nt < 16; nt++) {
                #pragma unroll
                for (int c = 0; c < 2; c++) {
                    const int gcol = nt*8 + (lane & 3)*2 + c;
                    if (gcol > grow)     sacc[nt][c]     = -1e30f;
                    if (gcol > grow + 8) sacc[nt][2 + c] = -1e30f;
                }
            }
        }

        float tm0 = -1e30f, tm1 = -1e30f;
        #pragma unroll
        for (int nt = 0; nt < 16; nt++) {
            tm0 = fmaxf(tm0, fmaxf(sacc[nt][0], sacc[nt][1]));
            tm1 = fmaxf(tm1, fmaxf(sacc[nt][2], sacc[nt][3]));
        }
        tm0 = fmaxf(tm0, __shfl_xor_sync(0xffffffffu, tm0, 1));
        tm0 = fmaxf(tm0, __shfl_xor_sync(0xffffffffu, tm0, 2));
        tm1 = fmaxf(tm1, __shfl_xor_sync(0xffffffffu, tm1, 1));
        tm1 = fmaxf(tm1, __shfl_xor_sync(0xffffffffu, tm1, 2));
        const float mn0 = fmaxf(m0, tm0), mn1 = fmaxf(m1, tm1);
        const float al0 = __expf(m0 - mn0), al1 = __expf(m1 - mn1);

        uint32_t pf[16], pg[16];
        float rs0 = 0.f, rs1 = 0.f;
        #pragma unroll
        for (int nt = 0; nt < 16; nt++) {
            float p0 = __expf(sacc[nt][0] - mn0);
            float p1 = __expf(sacc[nt][1] - mn0);
            float p2 = __expf(sacc[nt][2] - mn1);
            float p3 = __expf(sacc[nt][3] - mn1);
            rs0 += p0 + p1; rs1 += p2 + p3;
            __half2 hp0 = __floats2half2_rn(p0, p1);
            __half2 hp1 = __floats2half2_rn(p2, p3);
            pf[nt] = *reinterpret_cast<uint32_t*>(&hp0);
            pg[nt] = *reinterpret_cast<uint32_t*>(&hp1);
        }
        rs0 += __shfl_xor_sync(0xffffffffu, rs0, 1);
        rs0 += __shfl_xor_sync(0xffffffffu, rs0, 2);
        rs1 += __shfl_xor_sync(0xffffffffu, rs1, 1);
        rs1 += __shfl_xor_sync(0xffffffffu, rs1, 2);
        l0 = l0 * al0 + rs0;  l1 = l1 * al1 + rs1;
        m0 = mn0;  m1 = mn1;
        #pragma unroll
        for (int nt = 0; nt < 8; nt++) {
            oacc[nt][0] *= al0; oacc[nt][1] *= al0;
            oacc[nt][2] *= al1; oacc[nt][3] *= al1;
        }

        #pragma unroll
        for (int t = 0; t < 8; t++) {
            uint32_t a[4] = { pf[2*t], pg[2*t], pf[2*t+1], pg[2*t+1] };
            const int kr = t*16 + vk_r;
            #pragma unroll
            for (int pp = 0; pp < 4; pp++) {
                uint32_t bt[4];
                LDSM4T(bt, sV + kr*128 + (((2*pp + vn_s) ^ (kr & 7)) << 4));
                mma_fp16(oacc[2*pp],   a, &bt[0]);
                mma_fp16(oacc[2*pp+1], a, &bt[2]);
            }
        }
    }

    const float inv0 = 1.0f / l0, inv1 = 1.0f / l1;
    const int row0 = it*128 + wid*16 + (lane >> 2);
    #pragma unroll
    for (int nt = 0; nt < 8; nt++) {
        const int col = h*64 + nt*8 + (lane & 3)*2;
        size_t o0 = (size_t)(b*SEQ + row0)     * DMODEL + col;
        size_t o1 = (size_t)(b*SEQ + row0 + 8) * DMODEL + col;
        *reinterpret_cast<__half2*>(Om + o0) = __floats2half2_rn(oacc[nt][0]*inv0, oacc[nt][1]*inv0);
        *reinterpret_cast<__half2*>(Om + o1) = __floats2half2_rn(oacc[nt][2]*inv1, oacc[nt][3]*inv1);
    }
}

// ---------------- orchestration ----------------
#define TGEMM_SMEM (3*32768 + 256)
#define FLASH_SMEM (16384 + 2*32768 + 256)

extern "C" void kernel_launch(void* const* d_in, const int* in_sizes, int n_in,
                              void* d_out, int out_size)
{
    (void)in_sizes; (void)n_in; (void)out_size;
    const float* x    = (const float*)d_in[0];
    const float* Wq   = (const float*)d_in[1];
    const float* bq   = (const float*)d_in[2];
    const float* Wk   = (const float*)d_in[3];
    const float* bk   = (const float*)d_in[4];
    const float* Wv   = (const float*)d_in[5];
    const float* bv   = (const float*)d_in[6];
    const float* Wo   = (const float*)d_in[7];
    const float* bo   = (const float*)d_in[8];
    const float* ln1g = (const float*)d_in[9];
    const float* ln1b = (const float*)d_in[10];
    const float* ln2g = (const float*)d_in[11];
    const float* ln2b = (const float*)d_in[12];
    const float* W1   = (const float*)d_in[13];
    const float* b1   = (const float*)d_in[14];
    const float* W2   = (const float*)d_in[15];
    const float* b2   = (const float*)d_in[16];
    float* out = (float*)d_out;

    cudaFuncSetAttribute(tgemm_kernel<1>, cudaFuncAttributeMaxDynamicSharedMemorySize, TGEMM_SMEM);
    cudaFuncSetAttribute(tgemm_kernel<2>, cudaFuncAttributeMaxDynamicSharedMemorySize, TGEMM_SMEM);
    cudaFuncSetAttribute(tgemm_kernel<3>, cudaFuncAttributeMaxDynamicSharedMemorySize, TGEMM_SMEM);
    cudaFuncSetAttribute(tgemm_kernel<5>, cudaFuncAttributeMaxDynamicSharedMemorySize, TGEMM_SMEM);
    cudaFuncSetAttribute(flash_kernel,    cudaFuncAttributeMaxDynamicSharedMemorySize, FLASH_SMEM);

    // one-time side stream + events (created on the first, non-captured call)
    static cudaStream_t s_side = nullptr;
    static cudaEvent_t  s_ev0 = nullptr, s_ev1 = nullptr;
    if (!s_side) {
        cudaStreamCreateWithFlags(&s_side, cudaStreamNonBlocking);
        cudaEventCreateWithFlags(&s_ev0, cudaEventDisableTiming);
        cudaEventCreateWithFlags(&s_ev1, cudaEventDisableTiming);
    }

    __half *p_ln1, *p_ln2, *p_att, *p_ff, *p_qkv, *p_x1;
    __half *p_wqkv, *p_wo, *p_w1, *p_w2;
    float *p_bqkv;
    cudaGetSymbolAddress((void**)&p_ln1,  g_ln1);
    cudaGetSymbolAddress((void**)&p_ln2,  g_ln2);
    cudaGetSymbolAddress((void**)&p_att,  g_att);
    cudaGetSymbolAddress((void**)&p_ff,   g_ff);
    cudaGetSymbolAddress((void**)&p_qkv,  g_qkv);
    cudaGetSymbolAddress((void**)&p_wqkv, g_wqkv);
    cudaGetSymbolAddress((void**)&p_wo,   g_wo);
    cudaGetSymbolAddress((void**)&p_w1,   g_w1);
    cudaGetSymbolAddress((void**)&p_w2,   g_w2);
    cudaGetSymbolAddress((void**)&p_x1,   g_x1);
    cudaGetSymbolAddress((void**)&p_bqkv, g_bqkv);

    // ---- fork: weight prep on side stream, LN1 on main stream ----
    cudaEventRecord(s_ev0, 0);
    cudaStreamWaitEvent(s_side, s_ev0, 0);
    wsplit_all_kernel<<<12288, dim3(32, 8), 0, s_side>>>(Wq, Wk, Wv, Wo, W1, W2,
                                                         p_wqkv, p_wo, p_w1, p_w2);
    bcat_kernel<<<QKVN/256, 256, 0, s_side>>>(bq, bk, bv, p_bqkv);
    cudaEventRecord(s_ev1, s_side);

    ln_kernel<float><<<MROWS, 256>>>(x, ln1g, ln1b, p_ln1);
    cudaStreamWaitEvent(0, s_ev1, 0);
    // ---- join ----

    tgemm_kernel<5><<<dim3(QKVN/128, MROWS/128), 256, TGEMM_SMEM>>>(
        p_ln1, p_wqkv, p_bqkv, nullptr, nullptr, nullptr, p_qkv, DMODEL, QKVN);

    flash_kernel<<<dim3(SEQ/128, BHCNT), 256, FLASH_SMEM>>>(p_qkv, p_att);

    const dim3 gDD(DMODEL/128, MROWS/128);   // (8, 64)
    tgemm_kernel<2><<<gDD, 256, TGEMM_SMEM>>>(p_att, p_wo, bo, x, nullptr, nullptr, p_x1, DMODEL, DMODEL);
    ln_kernel<__half><<<MROWS, 256>>>(p_x1, ln2g, ln2b, p_ln2);
    tgemm_kernel<1><<<dim3(DFF/128, MROWS/128), 256, TGEMM_SMEM>>>(
        p_ln2, p_w1, b1, nullptr, nullptr, nullptr, p_ff, DMODEL, DFF);
    tgemm_kernel<3><<<gDD, 256, TGEMM_SMEM>>>(p_ff, p_w2, b2, nullptr, p_x1, out, nullptr, DFF, DMODEL);
}